// round 13
// baseline (speedup 1.0000x reference)
#include <cuda_runtime.h>
#include <cstdint>
#include <cstddef>

#define NB 8
#define NA 750000
#define PRE_NMS 4000
#define POST_NMS 1000
#define MIN_SIZE 0.001f
#define IMG_WF 1000.0f
#define IMG_HF 1000.0f
#define CAND_CAP 8192
#define STG_CAP 32768   /* staged candidates (key >= T_STAGE) per image */
#define SBUF 1024
#define WPR 64          /* mask words per row (63 used; word 63 never written -> 0) */
#define BBOX_CLIP 4.135166556742356f   /* log(1000/16) */
#define PEND 24         /* pipelined OR batch width (rows) */
#define C_HI 0.700007f
#define C_LO 0.699993f
#define T_STAGE 0xC0000000u   /* fkey(2.0f): static staging threshold */

typedef unsigned long long u64;

// ---------------- scratch (static device allocations; zero-initialized) ----
__device__ int      g_fbflag[NB];
__device__ int      g_cand_cnt[NB];
__device__ int      g_scnt[NB];            // staged count
__device__ u64      g_cand[NB * CAND_CAP];
__device__ u64      g_stg[NB * STG_CAP];
__device__ float4   g_box[NB * PRE_NMS];
__device__ float    g_prob[NB * PRE_NMS];
__device__ unsigned g_vmask32[NB * 128];
__device__ u64      g_mask[(size_t)NB * PRE_NMS * WPR];  // 16 MB

// monotone key: larger float -> larger unsigned
__device__ __forceinline__ unsigned fkey(float f) {
    unsigned u = __float_as_uint(f);
    return u ^ ((u & 0x80000000u) ? 0xFFFFFFFFu : 0x80000000u);
}
__device__ __forceinline__ float unkey(unsigned k) {
    return __uint_as_float((k & 0x80000000u) ? (k ^ 0x80000000u) : ~k);
}

// ---------------- K0: zero tiny scratch -------------------------------------
__global__ void k_zero() {
    int t = threadIdx.x;
    if (t < NB) { g_cand_cnt[t] = 0; g_scnt[t] = 0; g_fbflag[t] = 0; }
}

// ---------------- K1: pure staging pass (no histogram) ----------------------
__global__ void k_stage(const float* __restrict__ obj) {
    __shared__ u64 su[SBUF];
    __shared__ int sc, gbase;
    if (threadIdx.x == 0) sc = 0;
    __syncthreads();
    int img = blockIdx.y;
    const float4* o = (const float4*)(obj + (size_t)img * NA);
    int stride = gridDim.x * blockDim.x;
    for (int i = blockIdx.x * blockDim.x + threadIdx.x; i < NA / 4; i += stride) {
        float4 v = o[i];
        unsigned k0 = fkey(v.x), k1 = fkey(v.y), k2 = fkey(v.z), k3 = fkey(v.w);
        unsigned mx = max(max(k0, k1), max(k2, k3));
        if (mx >= T_STAGE) {               // rare (~2.3%): stage
#pragma unroll
            for (int j = 0; j < 4; j++) {
                unsigned key = (j == 0) ? k0 : (j == 1) ? k1 : (j == 2) ? k2 : k3;
                if (key < T_STAGE) continue;
                u64 e = ((u64)key << 32) | (unsigned)(~(unsigned)(4 * i + j));
                int p = atomicAdd(&sc, 1);
                if (p < SBUF) su[p] = e;
                else {
                    int q = atomicAdd(&g_scnt[img], 1);
                    if (q < STG_CAP) g_stg[img * STG_CAP + q] = e;
                }
            }
        }
    }
    __syncthreads();
    if (threadIdx.x == 0) {
        int a = sc < SBUF ? sc : SBUF;
        gbase = atomicAdd(&g_scnt[img], a);
    }
    __syncthreads();
    int ns = sc < SBUF ? sc : SBUF;
    for (int p = threadIdx.x; p < ns; p += blockDim.x) {
        int q = gbase + p;
        if (q < STG_CAP) g_stg[img * STG_CAP + q] = su[p];
    }
}

// ---------------- K2: select threshold from staged (4096-bin) + compact -----
__global__ void __launch_bounds__(1024) k_selects() {
    int img = blockIdx.x, tid = threadIdx.x, lane = tid & 31;
    __shared__ unsigned h[4096];
    __shared__ unsigned sh_T;
    __shared__ unsigned sh_scan[1024];
    for (int b = tid; b < 4096; b += 1024) h[b] = 0u;
    __syncthreads();
    int scnt = g_scnt[img];
    if (scnt < PRE_NMS || scnt > STG_CAP) {
        if (tid == 0) g_fbflag[img] = 1;   // staged set can't be proven complete
        return;
    }
    const u64* S = g_stg + img * STG_CAP;
    // histogram staged keys: bin = (key>>18) - 0x3000, range [0, 4096)
    for (int i = tid; i < scnt; i += 1024) {
        unsigned key = (unsigned)(S[i] >> 32);
        atomicAdd(&h[(key >> 18) - 0x3000u], 1u);
    }
    __syncthreads();
    // suffix scan: thread t owns 4 bins descending: 4095-4t .. 4092-4t
    unsigned part = h[4095 - 4 * tid] + h[4094 - 4 * tid] +
                    h[4093 - 4 * tid] + h[4092 - 4 * tid];
    sh_scan[tid] = part;
    __syncthreads();
    for (int off = 1; off < 1024; off <<= 1) {
        unsigned v = (tid >= off) ? sh_scan[tid - off] : 0u;
        __syncthreads();
        sh_scan[tid] += v;
        __syncthreads();
    }
    unsigned inc = sh_scan[tid];
    unsigned excl = inc - part;
    if (inc >= (unsigned)PRE_NMS && excl < (unsigned)PRE_NMS) {
        unsigned acc = excl;
        for (int kk = 0; kk < 4; kk++) {
            int b = 4095 - 4 * tid - kk;
            unsigned hv = h[b];
            if (acc + hv >= (unsigned)PRE_NMS) {
                sh_T = ((unsigned)b + 0x3000u) << 18;
                break;
            }
            acc += hv;
        }
    }
    __syncthreads();
    unsigned T = sh_T;
    // compact staged entries with key >= T (warp-aggregated)
    int nIter = (scnt + 1023) / 1024;
    for (int it = 0; it < nIter; it++) {
        int i = it * 1024 + tid;
        bool take = false;
        u64 e = 0ull;
        if (i < scnt) {
            e = S[i];
            take = ((unsigned)(e >> 32) >= T);
        }
        unsigned m = __ballot_sync(0xffffffffu, take);
        if (m) {
            int ldr = __ffs(m) - 1;
            int base = 0;
            if (lane == ldr) base = atomicAdd(&g_cand_cnt[img], __popc(m));
            base = __shfl_sync(0xffffffffu, base, ldr);
            if (take) {
                int p = base + __popc(m & ((1u << lane) - 1u));
                if (p < CAND_CAP) g_cand[img * CAND_CAP + p] = e;
            }
        }
    }
}

// ---------------- K3: FALLBACK full recompute, 1 block/image (gated) --------
__global__ void __launch_bounds__(1024) k_fallback(const float* __restrict__ obj) {
    int img = blockIdx.x;
    if (!g_fbflag[img]) return;
    __shared__ unsigned h[1024];
    __shared__ unsigned sh_b, sh_above, sh_T;
    __shared__ int cnt_s;
    int tid = threadIdx.x, lane = tid & 31;
    h[tid] = 0u;
    if (tid == 0) cnt_s = 0;
    __syncthreads();
    const float* o = obj + (size_t)img * NA;
    for (int i = tid; i < NA; i += 1024)
        atomicAdd(&h[fkey(o[i]) >> 22], 1u);
    __syncthreads();
    if (tid < 32) {                        // warp 0: coarse select
        unsigned part = 0;
        for (int r = lane * 32; r < lane * 32 + 32; r++) part += h[1023 - r];
        unsigned inc = part;
        for (int off = 1; off < 32; off <<= 1) {
            unsigned v = __shfl_up_sync(0xffffffffu, inc, off);
            if (lane >= off) inc += v;
        }
        unsigned excl = inc - part;
        if (inc >= (unsigned)PRE_NMS && excl < (unsigned)PRE_NMS) {
            unsigned acc = excl;
            for (int r = lane * 32; r < lane * 32 + 32; r++) {
                unsigned hv = h[1023 - r];
                if (acc + hv >= (unsigned)PRE_NMS) {
                    sh_b = (unsigned)(1023 - r);
                    sh_above = acc;
                    break;
                }
                acc += hv;
            }
        }
    }
    __syncthreads();
    unsigned c = sh_b;
    h[tid] = 0u;                           // reuse for fine histogram
    __syncthreads();
    for (int i = tid; i < NA; i += 1024) {
        unsigned key = fkey(o[i]);
        unsigned cb = key >> 22;
        if (cb < c) continue;
        u64 e = ((u64)key << 32) | (unsigned)(~(unsigned)i);
        if (cb > c) {
            int q = atomicAdd(&g_cand_cnt[img], 1);
            if (q < CAND_CAP) g_cand[img * CAND_CAP + q] = e;
        } else {
            atomicAdd(&h[(key >> 12) & 1023u], 1u);
            int q = atomicAdd(&cnt_s, 1);
            if (q < STG_CAP) g_stg[img * STG_CAP + q] = e;
        }
    }
    __syncthreads();
    if (tid < 32) {                        // warp 0: fine select
        unsigned part = 0;
        for (int r = lane * 32; r < lane * 32 + 32; r++) part += h[1023 - r];
        unsigned inc = part;
        for (int off = 1; off < 32; off <<= 1) {
            unsigned v = __shfl_up_sync(0xffffffffu, inc, off);
            if (lane >= off) inc += v;
        }
        unsigned needed = (unsigned)PRE_NMS - sh_above;
        unsigned excl = inc - part;
        if (inc >= needed && excl < needed) {
            unsigned acc = excl;
            for (int r = lane * 32; r < lane * 32 + 32; r++) {
                unsigned hv = h[1023 - r];
                if (acc + hv >= needed) {
                    sh_T = (c << 10) | (unsigned)(1023 - r);
                    break;
                }
                acc += hv;
            }
        }
    }
    __syncthreads();
    int bcnt = cnt_s < STG_CAP ? cnt_s : STG_CAP;
    for (int i = tid; i < bcnt; i += 1024) {
        u64 e = g_stg[img * STG_CAP + i];
        if ((unsigned)(e >> 44) >= sh_T) {
            int q = atomicAdd(&g_cand_cnt[img], 1);
            if (q < CAND_CAP) g_cand[img * CAND_CAP + q] = e;
        }
    }
}

// ---------------- K4: bitonic sort + decode + clip + sigmoid (fused) --------
__global__ void __launch_bounds__(1024, 1)
k_sortdecode(const float* __restrict__ deltas,
             const float* __restrict__ anchors) {
    extern __shared__ u64 s[];
    int img = blockIdx.x;
    int cnt = g_cand_cnt[img];
    if (cnt > CAND_CAP) cnt = CAND_CAP;
    unsigned S = (cnt <= 4096) ? 4096u : (unsigned)CAND_CAP;
    for (unsigned t = threadIdx.x; t < S; t += blockDim.x)
        s[t] = (t < (unsigned)cnt) ? g_cand[img * CAND_CAP + t] : 0ull;
    __syncthreads();
    for (unsigned k = 2; k <= S; k <<= 1) {
        for (unsigned j = k >> 1; j > 0; j >>= 1) {
            for (unsigned idx = threadIdx.x; idx < S; idx += blockDim.x) {
                unsigned ixj = idx ^ j;
                if (ixj > idx) {
                    u64 a = s[idx], b = s[ixj];
                    bool blk = ((idx & k) == 0u);     // descending overall
                    if (blk ? (a < b) : (a > b)) { s[idx] = b; s[ixj] = a; }
                }
            }
            __syncthreads();
        }
    }
    // decode top-4000 directly from sorted smem
    for (int t = threadIdx.x; t < 4096; t += blockDim.x) {
        bool inr = (t < PRE_NMS);
        u64 key = inr ? s[t] : 0ull;
        int idx = inr ? (int)(~(unsigned)key) : 0;
        float4 a = ((const float4*)anchors)[idx];
        float4 d = ((const float4*)deltas)[(size_t)img * NA + idx];
        float w = a.z - a.x, h = a.w - a.y;
        float cx = a.x + 0.5f * w, cy = a.y + 0.5f * h;
        float dw = fminf(d.z, BBOX_CLIP), dh = fminf(d.w, BBOX_CLIP);
        float pcx = d.x * w + cx, pcy = d.y * h + cy;
        float pw = expf(dw) * w, ph = expf(dh) * h;
        float x1 = pcx - 0.5f * pw, y1 = pcy - 0.5f * ph;
        float x2 = pcx + 0.5f * pw, y2 = pcy + 0.5f * ph;
        x1 = fminf(fmaxf(x1, 0.f), IMG_WF);
        y1 = fminf(fmaxf(y1, 0.f), IMG_HF);
        x2 = fminf(fmaxf(x2, 0.f), IMG_WF);
        y2 = fminf(fmaxf(y2, 0.f), IMG_HF);
        bool validb = false;
        if (inr) {
            g_box[img * PRE_NMS + t] = make_float4(x1, y1, x2, y2);
            validb = ((x2 - x1) >= MIN_SIZE) && ((y2 - y1) >= MIN_SIZE);
            float sc = unkey((unsigned)(key >> 32));
            g_prob[img * PRE_NMS + t] = 1.f / (1.f + expf(-sc));
        }
        unsigned bb = __ballot_sync(0xffffffffu, validb);
        if ((threadIdx.x & 31) == 0 && inr)
            g_vmask32[img * 128 + (t >> 5)] = bb;
    }
}

// ---------------- K5: dense IoU bitmask, 4 rows/thread (LDS amortized) ------
// sup: inter > c*(ra+car-inter)  <=>  (1+c)*inter - c*ra > c*car
__global__ void __launch_bounds__(128) k_iou() {
    int img = blockIdx.z, rb = blockIdx.y, cb = blockIdx.x;
    int row0 = rb * 512;
    if (cb * 64 + 64 <= row0) return;      // entire block below diagonal
    __shared__ float4 cbox[64];
    __shared__ float2 csc[64];
    int col0 = cb * 64;
    if (threadIdx.x < 64) {
        int c = col0 + threadIdx.x;
        float4 q = (c < PRE_NMS) ? g_box[img * PRE_NMS + c] : make_float4(0, 0, 0, 0);
        cbox[threadIdx.x] = q;
        float car = (q.z - q.x) * (q.w - q.y);
        csc[threadIdx.x] = make_float2(C_HI * car, C_LO * car);
    }
    __syncthreads();
    int row[4];
    bool wr[4];
    float4 r[4];
    float nhi[4], nlo[4], rav[4];
    unsigned mlo[4] = {0, 0, 0, 0}, mhi4[4] = {0, 0, 0, 0};
    unsigned blo[4] = {0, 0, 0, 0}, bhi4[4] = {0, 0, 0, 0};
#pragma unroll
    for (int k = 0; k < 4; k++) {
        row[k] = row0 + k * 128 + threadIdx.x;
        wr[k] = (row[k] < PRE_NMS) && (col0 + 63 > row[k]);
        int rclamp = wr[k] ? row[k] : 0;
        r[k] = g_box[img * PRE_NMS + rclamp];
        rav[k] = (r[k].z - r[k].x) * (r[k].w - r[k].y);
        nhi[k] = -C_HI * rav[k];
        nlo[k] = -C_LO * rav[k];
    }
#pragma unroll 8
    for (int j = 0; j < 64; j++) {
        float4 b = cbox[j];
        float2 sc = csc[j];
        unsigned bit = 1u << (j & 31);
#pragma unroll
        for (int k = 0; k < 4; k++) {
            float xx1 = fmaxf(r[k].x, b.x), yy1 = fmaxf(r[k].y, b.y);
            float xx2 = fminf(r[k].z, b.z), yy2 = fminf(r[k].w, b.w);
            float ww = fmaxf(xx2 - xx1, 0.f), hh = fmaxf(yy2 - yy1, 0.f);
            float inter = ww * hh;
            bool sup = __fmaf_rn(1.0f + C_HI, inter, nhi[k]) > sc.x;
            bool geq = __fmaf_rn(1.0f + C_LO, inter, nlo[k]) >= sc.y;
            if (j < 32) { mlo[k] |= sup ? bit : 0u; blo[k] |= geq ? bit : 0u; }
            else        { mhi4[k] |= sup ? bit : 0u; bhi4[k] |= geq ? bit : 0u; }
        }
    }
#pragma unroll
    for (int k = 0; k < 4; k++) {
        if (!wr[k]) continue;
        u64 msup  = ((u64)mhi4[k] << 32) | mlo[k];
        u64 mband = (((u64)bhi4[k] << 32) | blo[k]) & ~msup;
        int rel = row[k] - col0;           // keep only cols strictly above diag
        if (rel >= 0) {
            u64 hi = (rel >= 63) ? 0ull : (~0ull << (rel + 1));
            msup &= hi;
            mband &= hi;
        }
        while (mband) {                    // rare: bit-exact reference decision
            int j = __ffsll((long long)mband) - 1;
            mband &= mband - 1;
            float4 b = cbox[j];
            float carj = (b.z - b.x) * (b.w - b.y);
            float xx1 = fmaxf(r[k].x, b.x), yy1 = fmaxf(r[k].y, b.y);
            float xx2 = fminf(r[k].z, b.z), yy2 = fminf(r[k].w, b.w);
            float ww = fmaxf(xx2 - xx1, 0.f), hh = fmaxf(yy2 - yy1, 0.f);
            float inter = ww * hh;
            float uni = (rav[k] + carj) - inter;
            if ((inter / fmaxf(uni, 1e-9f)) > 0.7f) msup |= (1ull << j);
        }
        g_mask[((size_t)img * PRE_NMS + row[k]) * WPR + cb] = msup;
    }
}

// ---------------- K6: greedy NMS (pipelined OR) + output (fused) ------------
// layout: [proposals (8,1000,4) f32][scores (8,1000) f32]
__global__ void __launch_bounds__(256)
k_nmsout(float* __restrict__ out) {
    int img = blockIdx.x;
    __shared__ u64 diag_sh[64];
    __shared__ u64 s_km[63];
    __shared__ int s_kept[POST_NMS];
    __shared__ int s_n;
    __shared__ unsigned sh[256];
    int tid = threadIdx.x;

    if (tid < 32) {                        // warp 0: sequential greedy scan
        int lane = tid;
        const unsigned* vm = g_vmask32 + img * 128;
        u64 r0 = ~((u64)vm[2 * lane] | ((u64)vm[2 * lane + 1] << 32));
        u64 r1 = ~((u64)vm[64 + 2 * lane] | ((u64)vm[65 + 2 * lane] << 32));
        const u64* M = g_mask + (size_t)img * PRE_NMS * WPR;
        u64 nd0 = M[(size_t)(2 * lane) * WPR + 0];
        u64 nd1 = M[(size_t)(2 * lane + 1) * WPR + 0];
        u64 pa[PEND], pb[PEND];            // pending OR loads (prev chunk keeps)
#pragma unroll
        for (int u = 0; u < PEND; u++) { pa[u] = 0ull; pb[u] = 0ull; }
        int n = 0;
        for (int ch = 0; ch < 63; ch++) {
            diag_sh[2 * lane] = nd0;
            diag_sh[2 * lane + 1] = nd1;
            __syncwarp();
            if (ch < 62) {                 // prefetch next chunk's diag
                int base = (ch + 1) * 64;
                int ra2 = base + 2 * lane, rb2 = ra2 + 1;
                nd0 = (ra2 < PRE_NMS) ? M[(size_t)ra2 * WPR + (ch + 1)] : 0ull;
                nd1 = (rb2 < PRE_NMS) ? M[(size_t)rb2 * WPR + (ch + 1)] : 0ull;
            }
            // consume pending OR loads from chunk ch-1's keeps
#pragma unroll
            for (int u = 0; u < PEND; u++) { r0 |= pa[u]; r1 |= pb[u]; }
            u64 remw = (ch < 32) ? __shfl_sync(0xffffffffu, r0, ch)
                                 : __shfl_sync(0xffffffffu, r1, ch - 32);
            u64 km = 0ull;
#pragma unroll
            for (int b = 0; b < 64; b += 2) {
                u64 d0 = diag_sh[b], d1 = diag_sh[b + 1];
                u64 d01 = d0 | d1;                 // off-chain
                u64 c01 = remw | d1;
                u64 c10 = remw | d0;
                u64 c11 = remw | d01;
                bool k0  = (remw & (1ull << b)) == 0ull;
                bool k1k = (c10  & (1ull << (b + 1))) == 0ull;
                bool k1s = (remw & (1ull << (b + 1))) == 0ull;
                u64 lo  = k0 ? c10 : remw;
                u64 hi2 = k0 ? c11 : c01;
                bool k1 = k0 ? k1k : k1s;
                remw = k1 ? hi2 : lo;
                km |= (k0 ? (1ull << b) : 0ull) | (k1 ? (1ull << (b + 1)) : 0ull);
            }
            // parallel kept-list extraction (rank by popcount)
            {
                bool kb0 = (km >> lane) & 1ull;
                int rk0 = __popcll(km & ((1ull << lane) - 1ull));
                int slot0 = n + rk0;
                if (kb0 && slot0 < POST_NMS) s_kept[slot0] = ch * 64 + lane;
                int l2 = lane + 32;
                bool kb1 = (km >> l2) & 1ull;
                int rk1 = __popcll(km & ((1ull << l2) - 1ull));
                int slot1 = n + rk1;
                if (kb1 && slot1 < POST_NMS) s_kept[slot1] = ch * 64 + l2;
            }
            if (lane == 0) s_km[ch] = km;
            n += __popcll(km);
            if (n >= POST_NMS) break;
            // issue OR loads for this chunk's keeps (consumed next iteration)
            u64 t = km;
#pragma unroll
            for (int u = 0; u < PEND; u++) {
                int rr = -1;
                if (t) { rr = ch * 64 + (__ffsll((long long)t) - 1); t &= t - 1; }
                if (rr >= 0) {
                    const u64* rp = M + (size_t)rr * WPR;
                    pa[u] = rp[lane];
                    pb[u] = rp[32 + lane];   // word 63 never written -> 0
                } else { pa[u] = 0ull; pb[u] = 0ull; }
            }
            // overflow (>PEND keeps in one chunk): consume immediately
            while (t) {
                int rr8[8];
#pragma unroll
                for (int u = 0; u < 8; u++) {
                    if (t) { rr8[u] = ch * 64 + (__ffsll((long long)t) - 1); t &= t - 1; }
                    else    rr8[u] = -1;
                }
                u64 qa[8], qb[8];
#pragma unroll
                for (int u = 0; u < 8; u++) {
                    if (rr8[u] >= 0) {
                        const u64* rp = M + (size_t)rr8[u] * WPR;
                        qa[u] = rp[lane];
                        qb[u] = rp[32 + lane];
                    } else { qa[u] = 0ull; qb[u] = 0ull; }
                }
#pragma unroll
                for (int u = 0; u < 8; u++) { r0 |= qa[u]; r1 |= qb[u]; }
            }
            __syncwarp();
        }
        if (lane == 0) s_n = n;
    }
    __syncthreads();

    // ---- output assembly (256 threads) ----
    int n = s_n;
    int lim = n < POST_NMS ? n : POST_NMS;
    for (int s2 = tid; s2 < lim; s2 += 256) {
        int i = s_kept[s2];
        ((float4*)out)[img * POST_NMS + s2] = g_box[img * PRE_NMS + i];
        out[NB * POST_NMS * 4 + img * POST_NMS + s2] = g_prob[img * PRE_NMS + i];
    }
    if (n >= POST_NMS) return;
    // fill with non-kept indices ascending, score = -inf (top_k tie rule)
    unsigned base = 0;
    for (int chunk = 0; chunk < PRE_NMS; chunk += 256) {
        int i = chunk + tid;
        unsigned f = 0u;
        if (i < PRE_NMS) {
            u64 kw = s_km[i >> 6];
            f = ((kw >> (i & 63)) & 1ull) ? 0u : 1u;
        }
        sh[tid] = f;
        __syncthreads();
        for (int off = 1; off < 256; off <<= 1) {
            unsigned vv = (tid >= off) ? sh[tid - off] : 0u;
            __syncthreads();
            sh[tid] += vv;
            __syncthreads();
        }
        unsigned excl = sh[tid] - f;
        int slot = n + (int)(base + excl);
        if (f && slot < POST_NMS) {
            ((float4*)out)[img * POST_NMS + slot] = g_box[img * PRE_NMS + i];
            out[NB * POST_NMS * 4 + img * POST_NMS + slot] =
                __int_as_float(0xff800000);  // -inf
        }
        base += sh[255];
        __syncthreads();
    }
}

// ---------------- host ------------------------------------------------------
extern "C" void kernel_launch(void* const* d_in, const int* in_sizes, int n_in,
                              void* d_out, int out_size) {
    const float* obj     = (const float*)d_in[0];   // (8, 750000)
    const float* deltas  = (const float*)d_in[1];   // (8, 750000, 4)
    const float* anchors = (const float*)d_in[2];   // (750000, 4)
    float* out = (float*)d_out;

    k_zero<<<1, 32>>>();
    k_stage<<<dim3(144, NB), 256>>>(obj);
    k_selects<<<NB, 1024>>>();
    k_fallback<<<NB, 1024>>>(obj);             // no-op unless fallback

    cudaFuncSetAttribute(k_sortdecode, cudaFuncAttributeMaxDynamicSharedMemorySize,
                         CAND_CAP * (int)sizeof(u64));
    k_sortdecode<<<NB, 1024, CAND_CAP * sizeof(u64)>>>(deltas, anchors);

    k_iou<<<dim3(63, 8, NB), 128>>>();
    k_nmsout<<<NB, 256>>>(out);
}

// round 14
// speedup vs baseline: 1.2403x; 1.2403x over previous
#include <cuda_runtime.h>
#include <cstdint>
#include <cstddef>

#define NB 8
#define NA 750000
#define PRE_NMS 4000
#define POST_NMS 1000
#define MIN_SIZE 0.001f
#define IMG_WF 1000.0f
#define IMG_HF 1000.0f
#define CAND_CAP 8192
#define STG_CAP 32768   /* staged candidates (key >= T_STAGE) per image */
#define SBUF 1024
#define WPR 64          /* mask words per row (63 used; word 63 never written -> 0) */
#define BBOX_CLIP 4.135166556742356f   /* log(1000/16) */
#define PEND 24         /* pipelined OR batch width (rows) */
#define C_HI 0.700007f
#define C_LO 0.699993f
#define T_STAGE 0xC0000000u   /* fkey(2.0f): static staging threshold */

typedef unsigned long long u64;

// ---------------- scratch (static device allocations; zero-initialized) ----
__device__ int      g_fbflag[NB];
__device__ int      g_cand_cnt[NB];
__device__ int      g_scnt[NB];            // staged count
__device__ u64      g_cand[NB * CAND_CAP];
__device__ u64      g_stg[NB * STG_CAP];
__device__ float4   g_box[NB * PRE_NMS];
__device__ float    g_prob[NB * PRE_NMS];
__device__ unsigned g_vmask32[NB * 128];
__device__ u64      g_mask[(size_t)NB * PRE_NMS * WPR];  // 16 MB

// monotone key: larger float -> larger unsigned
__device__ __forceinline__ unsigned fkey(float f) {
    unsigned u = __float_as_uint(f);
    return u ^ ((u & 0x80000000u) ? 0xFFFFFFFFu : 0x80000000u);
}
__device__ __forceinline__ float unkey(unsigned k) {
    return __uint_as_float((k & 0x80000000u) ? (k ^ 0x80000000u) : ~k);
}

// ---------------- K0: zero tiny scratch -------------------------------------
__global__ void k_zero() {
    int t = threadIdx.x;
    if (t < NB) { g_cand_cnt[t] = 0; g_scnt[t] = 0; g_fbflag[t] = 0; }
}

// ---------------- K1: pure staging pass (no histogram) ----------------------
__global__ void k_stage(const float* __restrict__ obj) {
    __shared__ u64 su[SBUF];
    __shared__ int sc, gbase;
    if (threadIdx.x == 0) sc = 0;
    __syncthreads();
    int img = blockIdx.y;
    const float4* o = (const float4*)(obj + (size_t)img * NA);
    int stride = gridDim.x * blockDim.x;
    for (int i = blockIdx.x * blockDim.x + threadIdx.x; i < NA / 4; i += stride) {
        float4 v = o[i];
        unsigned k0 = fkey(v.x), k1 = fkey(v.y), k2 = fkey(v.z), k3 = fkey(v.w);
        unsigned mx = max(max(k0, k1), max(k2, k3));
        if (mx >= T_STAGE) {               // rare (~2.3%): stage
#pragma unroll
            for (int j = 0; j < 4; j++) {
                unsigned key = (j == 0) ? k0 : (j == 1) ? k1 : (j == 2) ? k2 : k3;
                if (key < T_STAGE) continue;
                u64 e = ((u64)key << 32) | (unsigned)(~(unsigned)(4 * i + j));
                int p = atomicAdd(&sc, 1);
                if (p < SBUF) su[p] = e;
                else {
                    int q = atomicAdd(&g_scnt[img], 1);
                    if (q < STG_CAP) g_stg[img * STG_CAP + q] = e;
                }
            }
        }
    }
    __syncthreads();
    if (threadIdx.x == 0) {
        int a = sc < SBUF ? sc : SBUF;
        gbase = atomicAdd(&g_scnt[img], a);
    }
    __syncthreads();
    int ns = sc < SBUF ? sc : SBUF;
    for (int p = threadIdx.x; p < ns; p += blockDim.x) {
        int q = gbase + p;
        if (q < STG_CAP) g_stg[img * STG_CAP + q] = su[p];
    }
}

// ---------------- K2: two-level select from staged + compact ----------------
// Level 1 bins key>>18 (4096 bins); level 2 refines the boundary bin on key
// bits [6,18) -> threshold granularity 64 key-units -> overshoot ~0-2.
__global__ void __launch_bounds__(1024) k_selects() {
    int img = blockIdx.x, tid = threadIdx.x, lane = tid & 31;
    __shared__ unsigned h[4096];
    __shared__ unsigned sh_scan[1024];
    __shared__ unsigned sh_B, sh_above, sh_T;
    for (int b = tid; b < 4096; b += 1024) h[b] = 0u;
    __syncthreads();
    int scnt = g_scnt[img];
    if (scnt < PRE_NMS || scnt > STG_CAP) {
        if (tid == 0) g_fbflag[img] = 1;   // staged set can't be proven complete
        return;
    }
    const u64* S = g_stg + img * STG_CAP;
    // ---- level 1: bin = (key>>18) - 0x3000 ----
    for (int i = tid; i < scnt; i += 1024) {
        unsigned key = (unsigned)(S[i] >> 32);
        atomicAdd(&h[(key >> 18) - 0x3000u], 1u);
    }
    __syncthreads();
    {   // suffix scan, 4 bins/thread descending
        unsigned part = h[4095 - 4 * tid] + h[4094 - 4 * tid] +
                        h[4093 - 4 * tid] + h[4092 - 4 * tid];
        sh_scan[tid] = part;
        __syncthreads();
        for (int off = 1; off < 1024; off <<= 1) {
            unsigned v = (tid >= off) ? sh_scan[tid - off] : 0u;
            __syncthreads();
            sh_scan[tid] += v;
            __syncthreads();
        }
        unsigned inc = sh_scan[tid];
        unsigned excl = inc - part;
        if (inc >= (unsigned)PRE_NMS && excl < (unsigned)PRE_NMS) {
            unsigned acc = excl;
            for (int kk = 0; kk < 4; kk++) {
                int b = 4095 - 4 * tid - kk;
                unsigned hv = h[b];
                if (acc + hv >= (unsigned)PRE_NMS) {
                    sh_B = (unsigned)b;
                    sh_above = acc;            // strictly-above-bin count
                    break;
                }
                acc += hv;
            }
        }
    }
    __syncthreads();
    unsigned B = sh_B, above = sh_above;
    // ---- level 2: refine inside boundary bin on bits [6,18) ----
    for (int b = tid; b < 4096; b += 1024) h[b] = 0u;
    __syncthreads();
    for (int i = tid; i < scnt; i += 1024) {
        unsigned key = (unsigned)(S[i] >> 32);
        if (((key >> 18) - 0x3000u) == B)
            atomicAdd(&h[(key >> 6) & 0xFFFu], 1u);
    }
    __syncthreads();
    {
        unsigned part = h[4095 - 4 * tid] + h[4094 - 4 * tid] +
                        h[4093 - 4 * tid] + h[4092 - 4 * tid];
        sh_scan[tid] = part;
        __syncthreads();
        for (int off = 1; off < 1024; off <<= 1) {
            unsigned v = (tid >= off) ? sh_scan[tid - off] : 0u;
            __syncthreads();
            sh_scan[tid] += v;
            __syncthreads();
        }
        unsigned needed = (unsigned)PRE_NMS - above;
        unsigned inc = sh_scan[tid];
        unsigned excl = inc - part;
        if (inc >= needed && excl < needed) {
            unsigned acc = excl;
            for (int kk = 0; kk < 4; kk++) {
                int b = 4095 - 4 * tid - kk;
                unsigned hv = h[b];
                if (acc + hv >= needed) {
                    sh_T = ((B + 0x3000u) << 18) | ((unsigned)b << 6);
                    break;
                }
                acc += hv;
            }
        }
    }
    __syncthreads();
    unsigned T = sh_T;
    // compact staged entries with key >= T (warp-aggregated)
    int nIter = (scnt + 1023) / 1024;
    for (int it = 0; it < nIter; it++) {
        int i = it * 1024 + tid;
        bool take = false;
        u64 e = 0ull;
        if (i < scnt) {
            e = S[i];
            take = ((unsigned)(e >> 32) >= T);
        }
        unsigned m = __ballot_sync(0xffffffffu, take);
        if (m) {
            int ldr = __ffs(m) - 1;
            int base = 0;
            if (lane == ldr) base = atomicAdd(&g_cand_cnt[img], __popc(m));
            base = __shfl_sync(0xffffffffu, base, ldr);
            if (take) {
                int p = base + __popc(m & ((1u << lane) - 1u));
                if (p < CAND_CAP) g_cand[img * CAND_CAP + p] = e;
            }
        }
    }
}

// ---------------- K3: FALLBACK full recompute, 1 block/image (gated) --------
__global__ void __launch_bounds__(1024) k_fallback(const float* __restrict__ obj) {
    int img = blockIdx.x;
    if (!g_fbflag[img]) return;
    __shared__ unsigned h[1024];
    __shared__ unsigned sh_b, sh_above, sh_T;
    __shared__ int cnt_s;
    int tid = threadIdx.x, lane = tid & 31;
    h[tid] = 0u;
    if (tid == 0) cnt_s = 0;
    __syncthreads();
    const float* o = obj + (size_t)img * NA;
    for (int i = tid; i < NA; i += 1024)
        atomicAdd(&h[fkey(o[i]) >> 22], 1u);
    __syncthreads();
    if (tid < 32) {                        // warp 0: coarse select
        unsigned part = 0;
        for (int r = lane * 32; r < lane * 32 + 32; r++) part += h[1023 - r];
        unsigned inc = part;
        for (int off = 1; off < 32; off <<= 1) {
            unsigned v = __shfl_up_sync(0xffffffffu, inc, off);
            if (lane >= off) inc += v;
        }
        unsigned excl = inc - part;
        if (inc >= (unsigned)PRE_NMS && excl < (unsigned)PRE_NMS) {
            unsigned acc = excl;
            for (int r = lane * 32; r < lane * 32 + 32; r++) {
                unsigned hv = h[1023 - r];
                if (acc + hv >= (unsigned)PRE_NMS) {
                    sh_b = (unsigned)(1023 - r);
                    sh_above = acc;
                    break;
                }
                acc += hv;
            }
        }
    }
    __syncthreads();
    unsigned c = sh_b;
    h[tid] = 0u;                           // reuse for fine histogram
    __syncthreads();
    for (int i = tid; i < NA; i += 1024) {
        unsigned key = fkey(o[i]);
        unsigned cb = key >> 22;
        if (cb < c) continue;
        u64 e = ((u64)key << 32) | (unsigned)(~(unsigned)i);
        if (cb > c) {
            int q = atomicAdd(&g_cand_cnt[img], 1);
            if (q < CAND_CAP) g_cand[img * CAND_CAP + q] = e;
        } else {
            atomicAdd(&h[(key >> 12) & 1023u], 1u);
            int q = atomicAdd(&cnt_s, 1);
            if (q < STG_CAP) g_stg[img * STG_CAP + q] = e;
        }
    }
    __syncthreads();
    if (tid < 32) {                        // warp 0: fine select
        unsigned part = 0;
        for (int r = lane * 32; r < lane * 32 + 32; r++) part += h[1023 - r];
        unsigned inc = part;
        for (int off = 1; off < 32; off <<= 1) {
            unsigned v = __shfl_up_sync(0xffffffffu, inc, off);
            if (lane >= off) inc += v;
        }
        unsigned needed = (unsigned)PRE_NMS - sh_above;
        unsigned excl = inc - part;
        if (inc >= needed && excl < needed) {
            unsigned acc = excl;
            for (int r = lane * 32; r < lane * 32 + 32; r++) {
                unsigned hv = h[1023 - r];
                if (acc + hv >= needed) {
                    sh_T = (c << 10) | (unsigned)(1023 - r);
                    break;
                }
                acc += hv;
            }
        }
    }
    __syncthreads();
    int bcnt = cnt_s < STG_CAP ? cnt_s : STG_CAP;
    for (int i = tid; i < bcnt; i += 1024) {
        u64 e = g_stg[img * STG_CAP + i];
        if ((unsigned)(e >> 44) >= sh_T) {
            int q = atomicAdd(&g_cand_cnt[img], 1);
            if (q < CAND_CAP) g_cand[img * CAND_CAP + q] = e;
        }
    }
}

// ---------------- K4: bitonic sort + decode + clip + sigmoid (fused) --------
__global__ void __launch_bounds__(1024, 1)
k_sortdecode(const float* __restrict__ deltas,
             const float* __restrict__ anchors) {
    extern __shared__ u64 s[];
    int img = blockIdx.x;
    int cnt = g_cand_cnt[img];
    if (cnt > CAND_CAP) cnt = CAND_CAP;
    unsigned S = (cnt <= 4096) ? 4096u : (unsigned)CAND_CAP;
    for (unsigned t = threadIdx.x; t < S; t += blockDim.x)
        s[t] = (t < (unsigned)cnt) ? g_cand[img * CAND_CAP + t] : 0ull;
    __syncthreads();
    for (unsigned k = 2; k <= S; k <<= 1) {
        for (unsigned j = k >> 1; j > 0; j >>= 1) {
            for (unsigned idx = threadIdx.x; idx < S; idx += blockDim.x) {
                unsigned ixj = idx ^ j;
                if (ixj > idx) {
                    u64 a = s[idx], b = s[ixj];
                    bool blk = ((idx & k) == 0u);     // descending overall
                    if (blk ? (a < b) : (a > b)) { s[idx] = b; s[ixj] = a; }
                }
            }
            __syncthreads();
        }
    }
    // decode top-4000 directly from sorted smem
    for (int t = threadIdx.x; t < 4096; t += blockDim.x) {
        bool inr = (t < PRE_NMS);
        u64 key = inr ? s[t] : 0ull;
        int idx = inr ? (int)(~(unsigned)key) : 0;
        float4 a = ((const float4*)anchors)[idx];
        float4 d = ((const float4*)deltas)[(size_t)img * NA + idx];
        float w = a.z - a.x, h = a.w - a.y;
        float cx = a.x + 0.5f * w, cy = a.y + 0.5f * h;
        float dw = fminf(d.z, BBOX_CLIP), dh = fminf(d.w, BBOX_CLIP);
        float pcx = d.x * w + cx, pcy = d.y * h + cy;
        float pw = expf(dw) * w, ph = expf(dh) * h;
        float x1 = pcx - 0.5f * pw, y1 = pcy - 0.5f * ph;
        float x2 = pcx + 0.5f * pw, y2 = pcy + 0.5f * ph;
        x1 = fminf(fmaxf(x1, 0.f), IMG_WF);
        y1 = fminf(fmaxf(y1, 0.f), IMG_HF);
        x2 = fminf(fmaxf(x2, 0.f), IMG_WF);
        y2 = fminf(fmaxf(y2, 0.f), IMG_HF);
        bool validb = false;
        if (inr) {
            g_box[img * PRE_NMS + t] = make_float4(x1, y1, x2, y2);
            validb = ((x2 - x1) >= MIN_SIZE) && ((y2 - y1) >= MIN_SIZE);
            float sc = unkey((unsigned)(key >> 32));
            g_prob[img * PRE_NMS + t] = 1.f / (1.f + expf(-sc));
        }
        unsigned bb = __ballot_sync(0xffffffffu, validb);
        if ((threadIdx.x & 31) == 0 && inr)
            g_vmask32[img * 128 + (t >> 5)] = bb;
    }
}

// ---------------- K5: dense IoU bitmask (256 rows/block, shaved loop) -------
// sup: inter > c*(ra+car-inter)  <=>  (1+c)*inter - c*ra > c*car
__global__ void __launch_bounds__(256) k_iou() {
    int img = blockIdx.z, rb = blockIdx.y, cb = blockIdx.x;
    if (cb * 64 + 64 <= rb * 256) return;  // entire col-block below diagonal
    __shared__ float4 cbox[64];
    __shared__ float2 csc[64];
    int col0 = cb * 64;
    if (threadIdx.x < 64) {
        int c = col0 + threadIdx.x;
        float4 q = (c < PRE_NMS) ? g_box[img * PRE_NMS + c] : make_float4(0, 0, 0, 0);
        cbox[threadIdx.x] = q;
        float car = (q.z - q.x) * (q.w - q.y);
        csc[threadIdx.x] = make_float2(C_HI * car, C_LO * car);
    }
    __syncthreads();
    int row = rb * 256 + threadIdx.x;
    if (row >= PRE_NMS) return;
    if (col0 + 63 <= row) return;          // this row's word all below/equal diag
    float4 r = g_box[img * PRE_NMS + row];
    float ra = (r.z - r.x) * (r.w - r.y);
    float nra_hi = -C_HI * ra;
    float nra_lo = -C_LO * ra;
    unsigned mlo = 0u, mhi = 0u, blo = 0u, bhi = 0u;
#pragma unroll 16
    for (int j = 0; j < 64; j++) {
        float4 b = cbox[j];
        float2 sc = csc[j];
        float xx1 = fmaxf(r.x, b.x), yy1 = fmaxf(r.y, b.y);
        float xx2 = fminf(r.z, b.z), yy2 = fminf(r.w, b.w);
        float ww = fmaxf(xx2 - xx1, 0.f), hh = fmaxf(yy2 - yy1, 0.f);
        float inter = ww * hh;
        bool sup = __fmaf_rn(1.0f + C_HI, inter, nra_hi) > sc.x;
        bool geq = __fmaf_rn(1.0f + C_LO, inter, nra_lo) >= sc.y;
        unsigned bit = 1u << (j & 31);
        if (j < 32) { mlo |= sup ? bit : 0u; blo |= geq ? bit : 0u; }
        else        { mhi |= sup ? bit : 0u; bhi |= geq ? bit : 0u; }
    }
    u64 msup  = ((u64)mhi << 32) | mlo;
    u64 mband = (((u64)bhi << 32) | blo) & ~msup;
    int rel = row - col0;                  // keep only cols strictly above diag
    if (rel >= 0) {
        u64 hi = (rel >= 63) ? 0ull : (~0ull << (rel + 1));
        msup &= hi;
        mband &= hi;
    }
    while (mband) {                        // rare: bit-exact reference decision
        int j = __ffsll((long long)mband) - 1;
        mband &= mband - 1;
        float4 b = cbox[j];
        float carj = (b.z - b.x) * (b.w - b.y);
        float xx1 = fmaxf(r.x, b.x), yy1 = fmaxf(r.y, b.y);
        float xx2 = fminf(r.z, b.z), yy2 = fminf(r.w, b.w);
        float ww = fmaxf(xx2 - xx1, 0.f), hh = fmaxf(yy2 - yy1, 0.f);
        float inter = ww * hh;
        float uni = (ra + carj) - inter;
        if ((inter / fmaxf(uni, 1e-9f)) > 0.7f) msup |= (1ull << j);
    }
    g_mask[((size_t)img * PRE_NMS + row) * WPR + cb] = msup;
}

// ---------------- K6: greedy NMS (pipelined OR) + output (fused) ------------
// layout: [proposals (8,1000,4) f32][scores (8,1000) f32]
__global__ void __launch_bounds__(256)
k_nmsout(float* __restrict__ out) {
    int img = blockIdx.x;
    __shared__ u64 diag_sh[64];
    __shared__ u64 s_km[63];
    __shared__ int s_kept[POST_NMS];
    __shared__ int s_n;
    __shared__ unsigned sh[256];
    int tid = threadIdx.x;

    if (tid < 32) {                        // warp 0: sequential greedy scan
        int lane = tid;
        const unsigned* vm = g_vmask32 + img * 128;
        u64 r0 = ~((u64)vm[2 * lane] | ((u64)vm[2 * lane + 1] << 32));
        u64 r1 = ~((u64)vm[64 + 2 * lane] | ((u64)vm[65 + 2 * lane] << 32));
        const u64* M = g_mask + (size_t)img * PRE_NMS * WPR;
        u64 nd0 = M[(size_t)(2 * lane) * WPR + 0];
        u64 nd1 = M[(size_t)(2 * lane + 1) * WPR + 0];
        u64 pa[PEND], pb[PEND];            // pending OR loads (prev chunk keeps)
#pragma unroll
        for (int u = 0; u < PEND; u++) { pa[u] = 0ull; pb[u] = 0ull; }
        int n = 0;
        for (int ch = 0; ch < 63; ch++) {
            diag_sh[2 * lane] = nd0;
            diag_sh[2 * lane + 1] = nd1;
            __syncwarp();
            if (ch < 62) {                 // prefetch next chunk's diag
                int base = (ch + 1) * 64;
                int ra2 = base + 2 * lane, rb2 = ra2 + 1;
                nd0 = (ra2 < PRE_NMS) ? M[(size_t)ra2 * WPR + (ch + 1)] : 0ull;
                nd1 = (rb2 < PRE_NMS) ? M[(size_t)rb2 * WPR + (ch + 1)] : 0ull;
            }
            // consume pending OR loads from chunk ch-1's keeps
#pragma unroll
            for (int u = 0; u < PEND; u++) { r0 |= pa[u]; r1 |= pb[u]; }
            u64 remw = (ch < 32) ? __shfl_sync(0xffffffffu, r0, ch)
                                 : __shfl_sync(0xffffffffu, r1, ch - 32);
            u64 km = 0ull;
#pragma unroll
            for (int b = 0; b < 64; b += 2) {
                u64 d0 = diag_sh[b], d1 = diag_sh[b + 1];
                u64 d01 = d0 | d1;                 // off-chain
                u64 c01 = remw | d1;
                u64 c10 = remw | d0;
                u64 c11 = remw | d01;
                bool k0  = (remw & (1ull << b)) == 0ull;
                bool k1k = (c10  & (1ull << (b + 1))) == 0ull;
                bool k1s = (remw & (1ull << (b + 1))) == 0ull;
                u64 lo  = k0 ? c10 : remw;
                u64 hi2 = k0 ? c11 : c01;
                bool k1 = k0 ? k1k : k1s;
                remw = k1 ? hi2 : lo;
                km |= (k0 ? (1ull << b) : 0ull) | (k1 ? (1ull << (b + 1)) : 0ull);
            }
            // parallel kept-list extraction (rank by popcount)
            {
                bool kb0 = (km >> lane) & 1ull;
                int rk0 = __popcll(km & ((1ull << lane) - 1ull));
                int slot0 = n + rk0;
                if (kb0 && slot0 < POST_NMS) s_kept[slot0] = ch * 64 + lane;
                int l2 = lane + 32;
                bool kb1 = (km >> l2) & 1ull;
                int rk1 = __popcll(km & ((1ull << l2) - 1ull));
                int slot1 = n + rk1;
                if (kb1 && slot1 < POST_NMS) s_kept[slot1] = ch * 64 + l2;
            }
            if (lane == 0) s_km[ch] = km;
            n += __popcll(km);
            if (n >= POST_NMS) break;
            // issue OR loads for this chunk's keeps (consumed next iteration)
            u64 t = km;
#pragma unroll
            for (int u = 0; u < PEND; u++) {
                int rr = -1;
                if (t) { rr = ch * 64 + (__ffsll((long long)t) - 1); t &= t - 1; }
                if (rr >= 0) {
                    const u64* rp = M + (size_t)rr * WPR;
                    pa[u] = rp[lane];
                    pb[u] = rp[32 + lane];   // word 63 never written -> 0
                } else { pa[u] = 0ull; pb[u] = 0ull; }
            }
            // overflow (>PEND keeps in one chunk): consume immediately
            while (t) {
                int rr8[8];
#pragma unroll
                for (int u = 0; u < 8; u++) {
                    if (t) { rr8[u] = ch * 64 + (__ffsll((long long)t) - 1); t &= t - 1; }
                    else    rr8[u] = -1;
                }
                u64 qa[8], qb[8];
#pragma unroll
                for (int u = 0; u < 8; u++) {
                    if (rr8[u] >= 0) {
                        const u64* rp = M + (size_t)rr8[u] * WPR;
                        qa[u] = rp[lane];
                        qb[u] = rp[32 + lane];
                    } else { qa[u] = 0ull; qb[u] = 0ull; }
                }
#pragma unroll
                for (int u = 0; u < 8; u++) { r0 |= qa[u]; r1 |= qb[u]; }
            }
            __syncwarp();
        }
        if (lane == 0) s_n = n;
    }
    __syncthreads();

    // ---- output assembly (256 threads) ----
    int n = s_n;
    int lim = n < POST_NMS ? n : POST_NMS;
    for (int s2 = tid; s2 < lim; s2 += 256) {
        int i = s_kept[s2];
        ((float4*)out)[img * POST_NMS + s2] = g_box[img * PRE_NMS + i];
        out[NB * POST_NMS * 4 + img * POST_NMS + s2] = g_prob[img * PRE_NMS + i];
    }
    if (n >= POST_NMS) return;
    // fill with non-kept indices ascending, score = -inf (top_k tie rule)
    unsigned base = 0;
    for (int chunk = 0; chunk < PRE_NMS; chunk += 256) {
        int i = chunk + tid;
        unsigned f = 0u;
        if (i < PRE_NMS) {
            u64 kw = s_km[i >> 6];
            f = ((kw >> (i & 63)) & 1ull) ? 0u : 1u;
        }
        sh[tid] = f;
        __syncthreads();
        for (int off = 1; off < 256; off <<= 1) {
            unsigned vv = (tid >= off) ? sh[tid - off] : 0u;
            __syncthreads();
            sh[tid] += vv;
            __syncthreads();
        }
        unsigned excl = sh[tid] - f;
        int slot = n + (int)(base + excl);
        if (f && slot < POST_NMS) {
            ((float4*)out)[img * POST_NMS + slot] = g_box[img * PRE_NMS + i];
            out[NB * POST_NMS * 4 + img * POST_NMS + slot] =
                __int_as_float(0xff800000);  // -inf
        }
        base += sh[255];
        __syncthreads();
    }
}

// ---------------- host ------------------------------------------------------
extern "C" void kernel_launch(void* const* d_in, const int* in_sizes, int n_in,
                              void* d_out, int out_size) {
    const float* obj     = (const float*)d_in[0];   // (8, 750000)
    const float* deltas  = (const float*)d_in[1];   // (8, 750000, 4)
    const float* anchors = (const float*)d_in[2];   // (750000, 4)
    float* out = (float*)d_out;

    k_zero<<<1, 32>>>();
    k_stage<<<dim3(144, NB), 256>>>(obj);
    k_selects<<<NB, 1024>>>();
    k_fallback<<<NB, 1024>>>(obj);             // no-op unless fallback

    cudaFuncSetAttribute(k_sortdecode, cudaFuncAttributeMaxDynamicSharedMemorySize,
                         CAND_CAP * (int)sizeof(u64));
    k_sortdecode<<<NB, 1024, CAND_CAP * sizeof(u64)>>>(deltas, anchors);

    k_iou<<<dim3(63, 16, NB), 256>>>();
    k_nmsout<<<NB, 256>>>(out);
}